// round 12
// baseline (speedup 1.0000x reference)
#include <cuda_runtime.h>
#include <cuda_fp16.h>
#include <cstdint>
#include <math.h>

#define BATCH 8
#define MDIM  16384
#define DDIM  512

// ---------------- scratch (device globals; no allocations allowed) ----------
__device__ __half g_x_hi[(size_t)BATCH * MDIM * DDIM];    // X hi (128MB)
__device__ __half g_x_lo[(size_t)BATCH * MDIM * DDIM];    // X lo (128MB)
__device__ float  g_energy[(size_t)BATCH * DDIM * DDIM];  // G    (8MB)
__device__ __half g_att[(size_t)BATCH * DDIM * DDIM];     // A    (4MB)

// ---------------- helpers ----------------
__device__ __forceinline__ uint32_t smem_u32(const void* p) {
    uint32_t a;
    asm("{ .reg .u64 t; cvta.to.shared.u64 t, %1; cvt.u32.u64 %0, t; }" : "=r"(a) : "l"(p));
    return a;
}
__device__ __forceinline__ void cp16(uint32_t dst, const void* src) {
    asm volatile("cp.async.cg.shared.global [%0], [%1], 16;" :: "r"(dst), "l"(src));
}
#define CP_COMMIT() asm volatile("cp.async.commit_group;" ::: "memory")
#define CP_WAIT(n)  asm volatile("cp.async.wait_group %0;" :: "n"(n) : "memory")

__device__ __forceinline__ void mma_f16(float* c, const uint32_t* a, const uint32_t* b) {
    asm volatile(
        "mma.sync.aligned.m16n8k16.row.col.f32.f16.f16.f32 "
        "{%0,%1,%2,%3}, {%4,%5,%6,%7}, {%8,%9}, {%0,%1,%2,%3};"
        : "+f"(c[0]), "+f"(c[1]), "+f"(c[2]), "+f"(c[3])
        : "r"(a[0]), "r"(a[1]), "r"(a[2]), "r"(a[3]), "r"(b[0]), "r"(b[1]));
}
__device__ __forceinline__ void ldsm4(uint32_t* r, uint32_t a) {
    asm volatile("ldmatrix.sync.aligned.m8n8.x4.shared.b16 {%0,%1,%2,%3}, [%4];"
                 : "=r"(r[0]), "=r"(r[1]), "=r"(r[2]), "=r"(r[3]) : "r"(a));
}
__device__ __forceinline__ void ldsm4t(uint32_t* r, uint32_t a) {
    asm volatile("ldmatrix.sync.aligned.m8n8.x4.trans.shared.b16 {%0,%1,%2,%3}, [%4];"
                 : "=r"(r[0]), "=r"(r[1]), "=r"(r[2]), "=r"(r[3]) : "r"(a));
}

// ---------------------------------------------------------------------------
// Kernel 0: fp16 hi/lo split of x + zero g_energy (fused). 32B stores.
// ---------------------------------------------------------------------------
__global__ void split_kernel(const float* __restrict__ x) {
    const size_t stride = (size_t)gridDim.x * blockDim.x;
    const size_t ne4 = (size_t)BATCH * DDIM * DDIM / 4;
    for (size_t i = (size_t)blockIdx.x * blockDim.x + threadIdx.x; i < ne4; i += stride)
        reinterpret_cast<float4*>(g_energy)[i] = make_float4(0.f, 0.f, 0.f, 0.f);
    const size_t n8 = (size_t)BATCH * MDIM * DDIM / 8;
    for (size_t i = (size_t)blockIdx.x * blockDim.x + threadIdx.x; i < n8; i += stride) {
        float4 v0 = reinterpret_cast<const float4*>(x)[2 * i];
        float4 v1 = reinterpret_cast<const float4*>(x)[2 * i + 1];
        float f[8] = {v0.x, v0.y, v0.z, v0.w, v1.x, v1.y, v1.z, v1.w};
        uint32_t hw[4], lw[4];
#pragma unroll
        for (int q = 0; q < 4; q++) {
            __half h0 = __float2half_rn(f[2 * q]);
            __half h1 = __float2half_rn(f[2 * q + 1]);
            __half l0 = __float2half_rn(f[2 * q] - __half2float(h0));
            __half l1 = __float2half_rn(f[2 * q + 1] - __half2float(h1));
            hw[q] = ((uint32_t)__half_as_ushort(h1) << 16) | __half_as_ushort(h0);
            lw[q] = ((uint32_t)__half_as_ushort(l1) << 16) | __half_as_ushort(l0);
        }
        reinterpret_cast<uint4*>(g_x_hi)[i] = make_uint4(hw[0], hw[1], hw[2], hw[3]);
        reinterpret_cast<uint4*>(g_x_lo)[i] = make_uint4(lw[0], lw[1], lw[2], lw[3]);
    }
}

// ---------------------------------------------------------------------------
// Kernel 1: Gram via mma.sync, symmetric pairs + K-split-16, 3-stage pipeline.
// Diagonal pairs (ti==tj) alias B panels onto A panels (half the loads).
// ---------------------------------------------------------------------------
#define G_LDA   272
#define G_TILE  (64 * G_LDA)      // 17408
#define G_STAGE (4 * G_TILE)      // 69632
#define G_SMEM  (3 * G_STAGE)     // 208896
#define KSPLIT  16
#define MCHUNK  (MDIM / KSPLIT)   // 1024

__constant__ int c_pair_ti[10] = {0,0,0,0,1,1,1,2,2,3};
__constant__ int c_pair_tj[10] = {0,1,2,3,1,2,3,2,3,3};

__device__ __forceinline__ void gram_load(uint32_t dst, const char* Ah, const char* Al,
                                          const char* Bh, const char* Bl, int m0, int tid,
                                          int ntiles) {
    const char* srcs[4] = {Ah, Al, Bh, Bl};
    for (int t = 0; t < ntiles; t++) {
        uint32_t db = dst + t * G_TILE;
        const char* sp = srcs[t] + (size_t)m0 * 1024;
#pragma unroll
        for (int j = 0; j < 2; j++) {
            int idx = tid + j * 512;
            int row = idx >> 4, c16 = idx & 15;
            cp16(db + row * G_LDA + c16 * 16, sp + (size_t)row * 1024 + c16 * 16);
        }
    }
}

extern __shared__ char dyn_smem[];

__global__ __launch_bounds__(512, 1) void gram_mma_kernel() {
    const uint32_t sb = smem_u32(dyn_smem);
    const int tid = threadIdx.x, l = tid & 31, w = tid >> 5;
    const int wm = w & 3, wn = w >> 2;            // warp tile: 32 (d) x 32 (e)
    const int b = blockIdx.z;
    const int ti = c_pair_ti[blockIdx.x], tj = c_pair_tj[blockIdx.x];
    const int d0 = ti * 128, e0 = tj * 128;
    const int mbase = blockIdx.y * MCHUNK;
    const bool offdiag = (ti != tj);
    const int ntiles = offdiag ? 4 : 2;
    const uint32_t boff = offdiag ? 2 * G_TILE : 0;   // B aliases A on diagonal

    const char* xh = (const char*)(g_x_hi + (size_t)b * MDIM * DDIM) + (size_t)mbase * 1024;
    const char* xl = (const char*)(g_x_lo + (size_t)b * MDIM * DDIM) + (size_t)mbase * 1024;
    const char* pAh = xh + d0 * 2;
    const char* pAl = xl + d0 * 2;
    const char* pBh = xh + e0 * 2;
    const char* pBl = xl + e0 * 2;

    float c[2][4][4];
#pragma unroll
    for (int i = 0; i < 2; i++)
#pragma unroll
        for (int j = 0; j < 4; j++)
#pragma unroll
            for (int q = 0; q < 4; q++) c[i][j][q] = 0.f;

    const int NIT = MCHUNK / 64;   // 16
    gram_load(sb + 0 * G_STAGE, pAh, pAl, pBh, pBl, 0, tid, ntiles);
    CP_COMMIT();
    gram_load(sb + 1 * G_STAGE, pAh, pAl, pBh, pBl, 64, tid, ntiles);
    CP_COMMIT();

    int s = 0;
    for (int it = 0; it < NIT; ++it) {
        if (it < NIT - 1) { CP_WAIT(1); } else { CP_WAIT(0); }
        __syncthreads();
        if (it + 2 < NIT) {
            int s2 = (s + 2 >= 3) ? (s - 1) : (s + 2);
            gram_load(sb + s2 * G_STAGE, pAh, pAl, pBh, pBl, (it + 2) * 64, tid, ntiles);
            CP_COMMIT();
        }
        const uint32_t st = sb + s * G_STAGE;

#pragma unroll
        for (int ks = 0; ks < 4; ks++) {
            uint32_t aH[2][4], aL[2][4], bH[4][2], bL[4][2];
            const int mrow = ks * 16 + ((l & 16) >> 1) + (l & 7);
            const uint32_t abase = st + mrow * G_LDA + (wm * 32 + (l & 8)) * 2;
#pragma unroll
            for (int ma = 0; ma < 2; ma++) {
                uint32_t ad = abase + ma * 32;
                ldsm4t(aH[ma], ad);
                ldsm4t(aL[ma], ad + G_TILE);
            }
            const uint32_t bbase = st + boff + mrow * G_LDA + (wn * 32 + (l & 8)) * 2;
#pragma unroll
            for (int p = 0; p < 2; p++) {
                uint32_t r[4];
                uint32_t bd = bbase + p * 32;
                ldsm4t(r, bd);
                bH[2 * p][0] = r[0]; bH[2 * p][1] = r[2];
                bH[2 * p + 1][0] = r[1]; bH[2 * p + 1][1] = r[3];
                ldsm4t(r, bd + G_TILE);
                bL[2 * p][0] = r[0]; bL[2 * p][1] = r[2];
                bL[2 * p + 1][0] = r[1]; bL[2 * p + 1][1] = r[3];
            }
#pragma unroll
            for (int ma = 0; ma < 2; ma++)
#pragma unroll
                for (int na = 0; na < 4; na++) {
                    mma_f16(c[ma][na], aH[ma], bH[na]);
                    mma_f16(c[ma][na], aH[ma], bL[na]);
                    mma_f16(c[ma][na], aL[ma], bH[na]);
                }
        }
        s = (s + 1 >= 3) ? 0 : (s + 1);
    }

    float* G = g_energy + (size_t)b * DDIM * DDIM;
#pragma unroll
    for (int ma = 0; ma < 2; ma++) {
        const int row0 = d0 + wm * 32 + ma * 16 + (l >> 2);
#pragma unroll
        for (int na = 0; na < 4; na++) {
            const int col = e0 + wn * 32 + na * 8 + (l & 3) * 2;
            atomicAdd(&G[(size_t)row0 * DDIM + col],           c[ma][na][0]);
            atomicAdd(&G[(size_t)row0 * DDIM + col + 1],       c[ma][na][1]);
            atomicAdd(&G[(size_t)(row0 + 8) * DDIM + col],     c[ma][na][2]);
            atomicAdd(&G[(size_t)(row0 + 8) * DDIM + col + 1], c[ma][na][3]);
            if (offdiag) {
                atomicAdd(&G[(size_t)col * DDIM + row0],           c[ma][na][0]);
                atomicAdd(&G[(size_t)(col + 1) * DDIM + row0],     c[ma][na][1]);
                atomicAdd(&G[(size_t)col * DDIM + row0 + 8],       c[ma][na][2]);
                atomicAdd(&G[(size_t)(col + 1) * DDIM + row0 + 8], c[ma][na][3]);
            }
        }
    }
}

// ---------------------------------------------------------------------------
// Kernel 2: softmax(-G) per row -> att fp16 ([d][e] layout)
// ---------------------------------------------------------------------------
__global__ void softmax_kernel() {
    const int b = blockIdx.y;
    const int d = blockIdx.x;
    const float* Grow = g_energy + (size_t)b * DDIM * DDIM + (size_t)d * DDIM;
    __half* A = g_att + (size_t)b * DDIM * DDIM + (size_t)d * DDIM;

    __shared__ float red[256];
    const int t = threadIdx.x;
    float v0 = Grow[t], v1 = Grow[t + 256];

    red[t] = fminf(v0, v1);
    __syncthreads();
#pragma unroll
    for (int s = 128; s > 0; s >>= 1) {
        if (t < s) red[t] = fminf(red[t], red[t + s]);
        __syncthreads();
    }
    const float gmin = red[0];
    __syncthreads();

    float p0 = expf(gmin - v0);
    float p1 = expf(gmin - v1);
    red[t] = p0 + p1;
    __syncthreads();
#pragma unroll
    for (int s = 128; s > 0; s >>= 1) {
        if (t < s) red[t] += red[t + s];
        __syncthreads();
    }
    const float inv = 1.f / red[0];
    A[t]       = __float2half_rn(p0 * inv);
    A[t + 256] = __float2half_rn(p1 * inv);
}

// ---------------------------------------------------------------------------
// Kernel 3: Y = gamma * (Xh @ Att^T) + X via mma.sync, 1 term.
// CTA 64(m)x128(d), 256 threads (8 warps, 2x4), warp tile 32x32.
// 4-stage pipeline, 110.6KB smem -> 2 CTAs/SM.
// ---------------------------------------------------------------------------
#define Q_LDA    144
#define QA_TILE  (64 * Q_LDA)      // 9216
#define QB_TILE  (128 * Q_LDA)     // 18432
#define Q_STAGE  (QA_TILE + QB_TILE)  // 27648
#define Q_NSTG   4
#define Q_SMEM   (Q_NSTG * Q_STAGE)   // 110592

__device__ __forceinline__ void g2_load(uint32_t dst, const char* Ah,
                                        const char* Bt, int k0, int tid) {
    // A: 64 rows x 8 c16 = 512 cp16
    {
        const char* sp = Ah + k0 * 2;
#pragma unroll
        for (int j = 0; j < 2; j++) {
            int idx = tid + j * 256;
            int row = idx >> 3, c16 = idx & 7;
            cp16(dst + row * Q_LDA + c16 * 16, sp + (size_t)row * 1024 + c16 * 16);
        }
    }
    // B: 128 rows x 8 c16 = 1024 cp16
    {
        const char* sp = Bt + k0 * 2;
        uint32_t db = dst + QA_TILE;
#pragma unroll
        for (int j = 0; j < 4; j++) {
            int idx = tid + j * 256;
            int row = idx >> 3, c16 = idx & 7;
            cp16(db + row * Q_LDA + c16 * 16, sp + (size_t)row * 1024 + c16 * 16);
        }
    }
}

__global__ __launch_bounds__(256, 2) void gemm2_mma_kernel(const float* __restrict__ x,
                                                           const float* __restrict__ gam,
                                                           float* __restrict__ out) {
    const uint32_t sb = smem_u32(dyn_smem);
    const int tid = threadIdx.x, l = tid & 31, w = tid >> 5;
    const int wm = w & 1, wn = w >> 1;            // warp tile: 32 (m) x 32 (d)
    const int b = blockIdx.z, d0 = blockIdx.x * 128, m0 = blockIdx.y * 64;

    const char* Ah = (const char*)(g_x_hi + (size_t)b * MDIM * DDIM + (size_t)m0 * DDIM);
    const char* Bt = (const char*)(g_att + (size_t)b * DDIM * DDIM + (size_t)d0 * DDIM);

    float c[2][4][4];
#pragma unroll
    for (int i = 0; i < 2; i++)
#pragma unroll
        for (int j = 0; j < 4; j++)
#pragma unroll
            for (int q = 0; q < 4; q++) c[i][j][q] = 0.f;

    const int NIT = DDIM / 64;    // 8
    g2_load(sb + 0 * Q_STAGE, Ah, Bt, 0, tid);
    CP_COMMIT();
    g2_load(sb + 1 * Q_STAGE, Ah, Bt, 64, tid);
    CP_COMMIT();
    g2_load(sb + 2 * Q_STAGE, Ah, Bt, 128, tid);
    CP_COMMIT();

    int s = 0;
    for (int it = 0; it < NIT; ++it) {
        if (it < NIT - 2)      { CP_WAIT(2); }
        else if (it == NIT - 2){ CP_WAIT(1); }
        else                   { CP_WAIT(0); }
        __syncthreads();
        if (it + 3 < NIT) {
            int s3 = s + 3; if (s3 >= Q_NSTG) s3 -= Q_NSTG;
            g2_load(sb + s3 * Q_STAGE, Ah, Bt, (it + 3) * 64, tid);
            CP_COMMIT();
        }
        const uint32_t st = sb + s * Q_STAGE;

#pragma unroll
        for (int ks = 0; ks < 4; ks++) {
            uint32_t aH[2][4], bb[4][2];
            const uint32_t akb = (ks * 16 + (l >> 4) * 8) * 2;
#pragma unroll
            for (int ma = 0; ma < 2; ma++) {
                const int arow = wm * 32 + ma * 16 + (l & 15);
                uint32_t ad = st + arow * Q_LDA + akb;
                ldsm4(aH[ma], ad);
            }
            {
                const int mloc = l >> 3;   // matrix index 0..3
#pragma unroll
                for (int p = 0; p < 2; p++) {
                    const int brow = wn * 32 + p * 16 + ((mloc >> 1) << 3) + (l & 7);
                    const uint32_t bkb = (ks * 16 + (mloc & 1) * 8) * 2;
                    uint32_t r[4];
                    ldsm4(r, st + QA_TILE + brow * Q_LDA + bkb);
                    bb[2 * p][0] = r[0]; bb[2 * p][1] = r[1];
                    bb[2 * p + 1][0] = r[2]; bb[2 * p + 1][1] = r[3];
                }
            }
#pragma unroll
            for (int ma = 0; ma < 2; ma++)
#pragma unroll
                for (int na = 0; na < 4; na++)
                    mma_f16(c[ma][na], aH[ma], bb[na]);
        }
        s = (s + 1 >= Q_NSTG) ? 0 : (s + 1);
    }

    const float gv = gam[0];
    const float* X = x + (size_t)b * MDIM * DDIM;
    float* Y = out + (size_t)b * MDIM * DDIM;
#pragma unroll
    for (int ma = 0; ma < 2; ma++) {
        const int row0 = m0 + wm * 32 + ma * 16 + (l >> 2);
#pragma unroll
        for (int na = 0; na < 4; na++) {
            const int col = d0 + wn * 32 + na * 8 + (l & 3) * 2;
            {
                float2 xv = *reinterpret_cast<const float2*>(X + (size_t)row0 * DDIM + col);
                *reinterpret_cast<float2*>(Y + (size_t)row0 * DDIM + col) =
                    make_float2(gv * c[ma][na][0] + xv.x, gv * c[ma][na][1] + xv.y);
            }
            {
                float2 xv = *reinterpret_cast<const float2*>(X + (size_t)(row0 + 8) * DDIM + col);
                *reinterpret_cast<float2*>(Y + (size_t)(row0 + 8) * DDIM + col) =
                    make_float2(gv * c[ma][na][2] + xv.x, gv * c[ma][na][3] + xv.y);
            }
        }
    }
}

// ---------------------------------------------------------------------------
extern "C" void kernel_launch(void* const* d_in, const int* in_sizes, int n_in,
                              void* d_out, int out_size) {
    const float* x     = (const float*)d_in[0];
    const float* gamma = (const float*)d_in[1];
    float* out = (float*)d_out;

    cudaFuncSetAttribute(gram_mma_kernel, cudaFuncAttributeMaxDynamicSharedMemorySize, G_SMEM);
    cudaFuncSetAttribute(gemm2_mma_kernel, cudaFuncAttributeMaxDynamicSharedMemorySize, Q_SMEM);

    split_kernel<<<2048, 256>>>(x);
    gram_mma_kernel<<<dim3(10, KSPLIT, BATCH), 512, G_SMEM>>>();
    softmax_kernel<<<dim3(DDIM, BATCH), 256>>>();
    gemm2_mma_kernel<<<dim3(4, MDIM / 64, BATCH), 256, Q_SMEM>>>(x, gamma, out);
}